// round 1
// baseline (speedup 1.0000x reference)
#include <cuda_runtime.h>

#define DM 512
#define BQ 64
#define LKV 4096
#define NB 32
#define NROWS (NB * BQ)            // 2048
#define SQRT_D 22.62741699796952f

// Scratch (device globals -- no allocation allowed)
__device__ float    g_Q[NROWS * DM];
__device__ float    g_A[NROWS * DM];
__device__ float    g_Y[NROWS * DM];
__device__ float    g_Z[NROWS];
__device__ unsigned g_M[NROWS];

// order-preserving float <-> uint key for atomicMax on floats
__device__ __forceinline__ unsigned f2key(float f) {
    unsigned b = __float_as_uint(f);
    return (b & 0x80000000u) ? ~b : (b | 0x80000000u);
}
__device__ __forceinline__ float key2f(unsigned u) {
    return (u & 0x80000000u) ? __uint_as_float(u & 0x7FFFFFFFu)
                             : __uint_as_float(~u);
}

__global__ void k_init() {
    int idx = blockIdx.x * blockDim.x + threadIdx.x;
    if (idx < NROWS * DM) g_Y[idx] = 0.0f;
    if (idx < NROWS) { g_Z[idx] = 0.0f; g_M[idx] = 0u; }
}

// ---------------------------------------------------------------------------
// NT GEMM: C[M,N] = A[M,K] * B[N,K]^T (+ bias, optional row scale 1/Z)
// BM=BN=64, BK=16, 256 threads, 4x4 per thread.
// MODE 0: C = x1 * wq^T + bq            (A=param,  C=g_Q)
// MODE 1: C = diag(1/Z) * g_Y * wv^T+bv (A=g_Y,    C=param d_out)
// ---------------------------------------------------------------------------
template <int MODE>
__global__ void k_gemm_nt(const float* __restrict__ Ag,
                          const float* __restrict__ Bg,
                          const float* __restrict__ bias,
                          float* __restrict__ Cg)
{
    __shared__ float As[64][20];
    __shared__ float Bs[64][20];
    const int m0 = blockIdx.x * 64;
    const int n0 = blockIdx.y * 64;
    const int t  = threadIdx.x;
    const int tr = t >> 4, tc = t & 15;
    const int lr = t >> 2, lc = (t & 3) << 2;

    const float* Asrc = (MODE == 0) ? Ag : (const float*)g_Y;
    float*       Cdst = (MODE == 0) ? (float*)g_Q : Cg;

    float acc[4][4] = {};
    const float* ap = Asrc + (m0 + lr) * DM + lc;
    const float* bp = Bg   + (n0 + lr) * DM + lc;

    for (int k0 = 0; k0 < DM; k0 += 16) {
        float4 av = *(const float4*)(ap + k0);
        float4 bv = *(const float4*)(bp + k0);
        As[lr][lc+0]=av.x; As[lr][lc+1]=av.y; As[lr][lc+2]=av.z; As[lr][lc+3]=av.w;
        Bs[lr][lc+0]=bv.x; Bs[lr][lc+1]=bv.y; Bs[lr][lc+2]=bv.z; Bs[lr][lc+3]=bv.w;
        __syncthreads();
        #pragma unroll
        for (int kk = 0; kk < 16; kk += 4) {
            float4 a4[4], b4[4];
            #pragma unroll
            for (int i = 0; i < 4; i++) a4[i] = *(const float4*)&As[tr*4+i][kk];
            #pragma unroll
            for (int j = 0; j < 4; j++) b4[j] = *(const float4*)&Bs[tc*4+j][kk];
            #pragma unroll
            for (int i = 0; i < 4; i++)
                #pragma unroll
                for (int j = 0; j < 4; j++)
                    acc[i][j] += a4[i].x*b4[j].x + a4[i].y*b4[j].y
                               + a4[i].z*b4[j].z + a4[i].w*b4[j].w;
        }
        __syncthreads();
    }

    #pragma unroll
    for (int i = 0; i < 4; i++) {
        const int row = m0 + tr*4 + i;
        float rs = 1.0f;
        if (MODE == 1) rs = 1.0f / g_Z[row];
        #pragma unroll
        for (int j = 0; j < 4; j++) {
            const int col = n0 + tc*4 + j;
            float v = acc[i][j];
            if (MODE == 1) v *= rs;
            Cdst[row * DM + col] = v + bias[col];
        }
    }
}

// ---------------------------------------------------------------------------
// NN GEMM: g_A = SQRT_D * (g_Q * wk)    [2048,512] x [512,512]
// ---------------------------------------------------------------------------
__global__ void k_gemm_nn_scale(const float* __restrict__ Bg)
{
    __shared__ float As[64][20];
    __shared__ float Bs[16][68];
    const int m0 = blockIdx.x * 64;
    const int n0 = blockIdx.y * 64;
    const int t  = threadIdx.x;
    const int tr = t >> 4, tc = t & 15;
    const int lrA = t >> 2,  lcA = (t & 3)  << 2;
    const int lrB = t >> 4,  lcB = (t & 15) << 2;

    float acc[4][4] = {};
    for (int k0 = 0; k0 < DM; k0 += 16) {
        float4 av = *(const float4*)&g_Q[(m0 + lrA) * DM + k0 + lcA];
        float4 bv = *(const float4*)&Bg[(k0 + lrB) * DM + n0 + lcB];
        As[lrA][lcA+0]=av.x; As[lrA][lcA+1]=av.y; As[lrA][lcA+2]=av.z; As[lrA][lcA+3]=av.w;
        Bs[lrB][lcB+0]=bv.x; Bs[lrB][lcB+1]=bv.y; Bs[lrB][lcB+2]=bv.z; Bs[lrB][lcB+3]=bv.w;
        __syncthreads();
        #pragma unroll
        for (int kk = 0; kk < 16; kk++) {
            float4 b4 = *(const float4*)&Bs[kk][tc*4];
            float a0 = As[tr*4+0][kk], a1 = As[tr*4+1][kk];
            float a2 = As[tr*4+2][kk], a3 = As[tr*4+3][kk];
            acc[0][0]+=a0*b4.x; acc[0][1]+=a0*b4.y; acc[0][2]+=a0*b4.z; acc[0][3]+=a0*b4.w;
            acc[1][0]+=a1*b4.x; acc[1][1]+=a1*b4.y; acc[1][2]+=a1*b4.z; acc[1][3]+=a1*b4.w;
            acc[2][0]+=a2*b4.x; acc[2][1]+=a2*b4.y; acc[2][2]+=a2*b4.z; acc[2][3]+=a2*b4.w;
            acc[3][0]+=a3*b4.x; acc[3][1]+=a3*b4.y; acc[3][2]+=a3*b4.z; acc[3][3]+=a3*b4.w;
        }
        __syncthreads();
    }
    #pragma unroll
    for (int i = 0; i < 4; i++) {
        const int row = m0 + tr*4 + i;
        #pragma unroll
        for (int j = 0; j < 4; j++)
            g_A[row * DM + n0 + tc*4 + j] = SQRT_D * acc[i][j];
    }
}

// ---------------------------------------------------------------------------
// Pass A: per-row max of S = A_b[64,512] . x2_b[512keys,512]^T
// grid (32 batches, 8 chunks of 512 keys), 256 threads
// ---------------------------------------------------------------------------
__global__ void k_score_max(const float* __restrict__ x2)
{
    __shared__ float As[64][20];
    __shared__ float Bs[64][20];
    __shared__ float red[16][64];
    const int b  = blockIdx.x;
    const int ch = blockIdx.y;
    const float* Ab = g_A + (long)b * BQ * DM;
    const float* Xb = x2 + ((long)b * LKV + (long)ch * 512) * DM;
    const int t  = threadIdx.x;
    const int tr = t >> 4, tc = t & 15;
    const int lr = t >> 2, lc = (t & 3) << 2;

    float rmax[4] = {-3.0e38f, -3.0e38f, -3.0e38f, -3.0e38f};

    for (int ns = 0; ns < 8; ns++) {
        float acc[4][4] = {};
        for (int k0 = 0; k0 < DM; k0 += 16) {
            float4 av = *(const float4*)&Ab[lr * DM + k0 + lc];
            float4 bv = *(const float4*)&Xb[(ns*64 + lr) * DM + k0 + lc];
            As[lr][lc+0]=av.x; As[lr][lc+1]=av.y; As[lr][lc+2]=av.z; As[lr][lc+3]=av.w;
            Bs[lr][lc+0]=bv.x; Bs[lr][lc+1]=bv.y; Bs[lr][lc+2]=bv.z; Bs[lr][lc+3]=bv.w;
            __syncthreads();
            #pragma unroll
            for (int kk = 0; kk < 16; kk += 4) {
                float4 a4[4], b4[4];
                #pragma unroll
                for (int i = 0; i < 4; i++) a4[i] = *(const float4*)&As[tr*4+i][kk];
                #pragma unroll
                for (int j = 0; j < 4; j++) b4[j] = *(const float4*)&Bs[tc*4+j][kk];
                #pragma unroll
                for (int i = 0; i < 4; i++)
                    #pragma unroll
                    for (int j = 0; j < 4; j++)
                        acc[i][j] += a4[i].x*b4[j].x + a4[i].y*b4[j].y
                                   + a4[i].z*b4[j].z + a4[i].w*b4[j].w;
            }
            __syncthreads();
        }
        #pragma unroll
        for (int i = 0; i < 4; i++)
            #pragma unroll
            for (int j = 0; j < 4; j++)
                rmax[i] = fmaxf(rmax[i], acc[i][j]);
    }

    #pragma unroll
    for (int i = 0; i < 4; i++) red[tc][tr*4+i] = rmax[i];
    __syncthreads();
    if (t < 64) {
        float m = red[0][t];
        #pragma unroll
        for (int c = 1; c < 16; c++) m = fmaxf(m, red[c][t]);
        atomicMax(&g_M[b * BQ + t], f2key(m));
    }
}

// ---------------------------------------------------------------------------
// Pass B: recompute S, p = exp(s - m); accumulate Z and (sparsely) Y += p*x2row
// Selected keys (s - m > -25) are rare (softmax is ~one-hot); warp-cooperative
// scatter-add of the 512-dim x2 row.
// ---------------------------------------------------------------------------
__global__ void k_score_accum(const float* __restrict__ x2)
{
    __shared__ float As[64][20];
    __shared__ float Bs[64][20];
    __shared__ float ms[64];
    __shared__ float redz[16][64];
    const int b  = blockIdx.x;
    const int ch = blockIdx.y;
    const float* Ab = g_A + (long)b * BQ * DM;
    const float* Xb = x2 + ((long)b * LKV + (long)ch * 512) * DM;
    const int t  = threadIdx.x;
    const int tr = t >> 4, tc = t & 15;
    const int lr = t >> 2, lc = (t & 3) << 2;
    const int lane = t & 31;

    if (t < 64) ms[t] = key2f(g_M[b * BQ + t]);
    __syncthreads();

    float zp[4] = {0.f, 0.f, 0.f, 0.f};

    for (int ns = 0; ns < 8; ns++) {
        float acc[4][4] = {};
        for (int k0 = 0; k0 < DM; k0 += 16) {
            float4 av = *(const float4*)&Ab[lr * DM + k0 + lc];
            float4 bv = *(const float4*)&Xb[(ns*64 + lr) * DM + k0 + lc];
            As[lr][lc+0]=av.x; As[lr][lc+1]=av.y; As[lr][lc+2]=av.z; As[lr][lc+3]=av.w;
            Bs[lr][lc+0]=bv.x; Bs[lr][lc+1]=bv.y; Bs[lr][lc+2]=bv.z; Bs[lr][lc+3]=bv.w;
            __syncthreads();
            #pragma unroll
            for (int kk = 0; kk < 16; kk += 4) {
                float4 a4[4], b4[4];
                #pragma unroll
                for (int i = 0; i < 4; i++) a4[i] = *(const float4*)&As[tr*4+i][kk];
                #pragma unroll
                for (int j = 0; j < 4; j++) b4[j] = *(const float4*)&Bs[tc*4+j][kk];
                #pragma unroll
                for (int i = 0; i < 4; i++)
                    #pragma unroll
                    for (int j = 0; j < 4; j++)
                        acc[i][j] += a4[i].x*b4[j].x + a4[i].y*b4[j].y
                                   + a4[i].z*b4[j].z + a4[i].w*b4[j].w;
            }
            __syncthreads();
        }
        // epilogue: softmax terms + sparse Y accumulation
        #pragma unroll
        for (int i = 0; i < 4; i++) {
            const float mrow = ms[tr*4 + i];
            const int   row  = b * BQ + tr*4 + i;
            #pragma unroll
            for (int j = 0; j < 4; j++) {
                float e   = acc[i][j] - mrow;
                bool  sel = (e > -25.0f);
                float p   = sel ? __expf(e) : 0.0f;
                zp[i] += p;
                unsigned msk = __ballot_sync(0xffffffffu, sel);
                int myk = ns*64 + tc*4 + j;
                while (msk) {
                    int src = __ffs(msk) - 1;
                    msk &= msk - 1;
                    float ps = __shfl_sync(0xffffffffu, p,   src);
                    int   ks = __shfl_sync(0xffffffffu, myk, src);
                    int   rs = __shfl_sync(0xffffffffu, row, src);
                    const float* xr = Xb + (long)ks * DM;
                    float*       yr = g_Y + (long)rs * DM;
                    for (int d = lane; d < DM; d += 32)
                        atomicAdd(&yr[d], ps * xr[d]);
                }
            }
        }
    }

    #pragma unroll
    for (int i = 0; i < 4; i++) redz[tc][tr*4+i] = zp[i];
    __syncthreads();
    if (t < 64) {
        float z = 0.0f;
        #pragma unroll
        for (int c = 0; c < 16; c++) z += redz[c][t];
        atomicAdd(&g_Z[b * BQ + t], z);
    }
}

// ---------------------------------------------------------------------------
extern "C" void kernel_launch(void* const* d_in, const int* in_sizes, int n_in,
                              void* d_out, int out_size)
{
    const float* x1 = (const float*)d_in[0];
    const float* x2 = (const float*)d_in[1];
    // d_in[2] = mask : unused in reference forward
    const float* wq = (const float*)d_in[3];
    const float* bq = (const float*)d_in[4];
    const float* wk = (const float*)d_in[5];
    // d_in[6] = bk : provably cancels in softmax (per-row constant)
    const float* wv = (const float*)d_in[7];
    const float* bv = (const float*)d_in[8];
    float* out = (float*)d_out;

    k_init<<<2048, 512>>>();

    // Q = x1 * wq^T + bq  -> g_Q
    k_gemm_nt<0><<<dim3(32, 8), 256>>>(x1, wq, bq, nullptr);

    // A = sqrt(d) * Q * wk -> g_A
    k_gemm_nn_scale<<<dim3(32, 8), 256>>>(wk);

    // pass A: row maxima of A . x2^T
    k_score_max<<<dim3(NB, 8), 256>>>(x2);

    // pass B: Z and sparse weighted-x2 accumulation Y
    k_score_accum<<<dim3(NB, 8), 256>>>(x2);

    // out = (Y / Z) * wv^T + bv
    k_gemm_nt<1><<<dim3(32, 8), 256>>>(nullptr, wv, bv, out);
}

// round 4
// speedup vs baseline: 4.9190x; 4.9190x over previous
#include <cuda_runtime.h>
#include <cuda_bf16.h>

#define DM 512
#define BQ 64
#define LKV 4096
#define NB 32
#define NROWS (NB * BQ)            // 2048
#define SQRT_D 22.62741699796952f
#define NCHUNK 16                  // key chunks per batch
#define CKEYS 256                  // keys per chunk
#define MAXC 64                    // candidate cap per row

// Scratch (device globals -- no allocation allowed)
__device__ float          g_Q[NROWS * DM];
__device__ float          g_A[NROWS * DM];
__device__ __nv_bfloat16  g_Ah[NROWS * DM];
__device__ float          g_Y[NROWS * DM];
__device__ float          g_S[NROWS * LKV];   // 33.5 MB bf16-TC scores (fp32 accum)
__device__ unsigned       g_M[NROWS];

__device__ __forceinline__ unsigned f2key(float f) {
    unsigned b = __float_as_uint(f);
    return (b & 0x80000000u) ? ~b : (b | 0x80000000u);
}
__device__ __forceinline__ float key2f(unsigned u) {
    return (u & 0x80000000u) ? __uint_as_float(u & 0x7FFFFFFFu)
                             : __uint_as_float(~u);
}

__global__ void k_init() {
    int idx = blockIdx.x * blockDim.x + threadIdx.x;
    if (idx < NROWS) g_M[idx] = 0u;
}

// ---------------------------------------------------------------------------
// NT GEMM: C[M,N] = A[M,K] * B[N,K]^T + bias   (fp32 exact path)
// MODE 0: g_Q = x1 * wq^T + bq
// MODE 1: out = g_Y * wv^T + bv    (g_Y already divided by Z)
// ---------------------------------------------------------------------------
template <int MODE>
__global__ void k_gemm_nt(const float* __restrict__ Ag,
                          const float* __restrict__ Bg,
                          const float* __restrict__ bias,
                          float* __restrict__ Cg)
{
    __shared__ float As[64][20];
    __shared__ float Bs[64][20];
    const int m0 = blockIdx.x * 64;
    const int n0 = blockIdx.y * 64;
    const int t  = threadIdx.x;
    const int tr = t >> 4, tc = t & 15;
    const int lr = t >> 2, lc = (t & 3) << 2;

    const float* Asrc = (MODE == 0) ? Ag : (const float*)g_Y;
    float*       Cdst = (MODE == 0) ? (float*)g_Q : Cg;

    float acc[4][4] = {};
    const float* ap = Asrc + (long)(m0 + lr) * DM + lc;
    const float* bp = Bg   + (long)(n0 + lr) * DM + lc;

    for (int k0 = 0; k0 < DM; k0 += 16) {
        float4 av = *(const float4*)(ap + k0);
        float4 bv = *(const float4*)(bp + k0);
        As[lr][lc+0]=av.x; As[lr][lc+1]=av.y; As[lr][lc+2]=av.z; As[lr][lc+3]=av.w;
        Bs[lr][lc+0]=bv.x; Bs[lr][lc+1]=bv.y; Bs[lr][lc+2]=bv.z; Bs[lr][lc+3]=bv.w;
        __syncthreads();
        #pragma unroll
        for (int kk = 0; kk < 16; kk += 4) {
            float4 a4[4], b4[4];
            #pragma unroll
            for (int i = 0; i < 4; i++) a4[i] = *(const float4*)&As[tr*4+i][kk];
            #pragma unroll
            for (int j = 0; j < 4; j++) b4[j] = *(const float4*)&Bs[tc*4+j][kk];
            #pragma unroll
            for (int i = 0; i < 4; i++)
                #pragma unroll
                for (int j = 0; j < 4; j++)
                    acc[i][j] += a4[i].x*b4[j].x + a4[i].y*b4[j].y
                               + a4[i].z*b4[j].z + a4[i].w*b4[j].w;
        }
        __syncthreads();
    }

    #pragma unroll
    for (int i = 0; i < 4; i++) {
        const int row = m0 + tr*4 + i;
        #pragma unroll
        for (int j = 0; j < 4; j++) {
            const int col = n0 + tc*4 + j;
            Cdst[(long)row * DM + col] = acc[i][j] + bias[col];
        }
    }
}

// ---------------------------------------------------------------------------
// NN GEMM: g_A = SQRT_D * (g_Q * wk), also emit bf16 copy g_Ah
// ---------------------------------------------------------------------------
__global__ void k_gemm_nn_scale(const float* __restrict__ Bg)
{
    __shared__ float As[64][20];
    __shared__ float Bs[16][68];
    const int m0 = blockIdx.x * 64;
    const int n0 = blockIdx.y * 64;
    const int t  = threadIdx.x;
    const int tr = t >> 4, tc = t & 15;
    const int lrA = t >> 2,  lcA = (t & 3)  << 2;
    const int lrB = t >> 4,  lcB = (t & 15) << 2;

    float acc[4][4] = {};
    for (int k0 = 0; k0 < DM; k0 += 16) {
        float4 av = *(const float4*)&g_Q[(long)(m0 + lrA) * DM + k0 + lcA];
        float4 bv = *(const float4*)&Bg[(long)(k0 + lrB) * DM + n0 + lcB];
        As[lrA][lcA+0]=av.x; As[lrA][lcA+1]=av.y; As[lrA][lcA+2]=av.z; As[lrA][lcA+3]=av.w;
        Bs[lrB][lcB+0]=bv.x; Bs[lrB][lcB+1]=bv.y; Bs[lrB][lcB+2]=bv.z; Bs[lrB][lcB+3]=bv.w;
        __syncthreads();
        #pragma unroll
        for (int kk = 0; kk < 16; kk++) {
            float4 b4 = *(const float4*)&Bs[kk][tc*4];
            float a0 = As[tr*4+0][kk], a1 = As[tr*4+1][kk];
            float a2 = As[tr*4+2][kk], a3 = As[tr*4+3][kk];
            acc[0][0]+=a0*b4.x; acc[0][1]+=a0*b4.y; acc[0][2]+=a0*b4.z; acc[0][3]+=a0*b4.w;
            acc[1][0]+=a1*b4.x; acc[1][1]+=a1*b4.y; acc[1][2]+=a1*b4.z; acc[1][3]+=a1*b4.w;
            acc[2][0]+=a2*b4.x; acc[2][1]+=a2*b4.y; acc[2][2]+=a2*b4.z; acc[2][3]+=a2*b4.w;
            acc[3][0]+=a3*b4.x; acc[3][1]+=a3*b4.y; acc[3][2]+=a3*b4.z; acc[3][3]+=a3*b4.w;
        }
        __syncthreads();
    }
    #pragma unroll
    for (int i = 0; i < 4; i++) {
        const int row = m0 + tr*4 + i;
        #pragma unroll
        for (int j = 0; j < 4; j++) {
            const int col = n0 + tc*4 + j;
            float v = SQRT_D * acc[i][j];
            g_A[(long)row * DM + col]  = v;
            g_Ah[(long)row * DM + col] = __float2bfloat16(v);
        }
    }
}

// ---------------------------------------------------------------------------
// Tensor-core score pass: S[b, q, k] = Ah[b,q,:] . x2h[b,k,:]  (bf16 mma,
// fp32 accum). Converts x2 fp32->bf16 in smem (x2 read exactly once).
// Also produces per-row max of the bf16 scores (atomicMax keyed).
// grid (32 batches, 16 chunks of 256 keys), 256 threads (8 warps x 32 keys).
// ---------------------------------------------------------------------------
__global__ void k_scores_tc(const float* __restrict__ x2)
{
    __shared__ __nv_bfloat16 Xs[CKEYS][40];   // 32-d slab, +8 pad (16B-aligned rows)
    __shared__ __nv_bfloat16 Avs[64][40];
    __shared__ unsigned red[64];

    const int b   = blockIdx.x;
    const int ch  = blockIdx.y;
    const int tid = threadIdx.x;
    const int w   = tid >> 5, lane = tid & 31;

    if (tid < 64) red[tid] = 0u;   // visible at epilogue: s-loop ends in __syncthreads

    float acc[4][4][4];
    #pragma unroll
    for (int m = 0; m < 4; m++)
        #pragma unroll
        for (int n = 0; n < 4; n++)
            #pragma unroll
            for (int c = 0; c < 4; c++) acc[m][n][c] = 0.0f;

    const float* Xg = x2 + ((long)b * LKV + (long)ch * CKEYS) * DM;
    const __nv_bfloat16* Ag = g_Ah + (long)b * BQ * DM;

    for (int s = 0; s < 16; s++) {
        // stage X slab: 256 keys x 32 d, fp32 -> bf16
        #pragma unroll
        for (int p = 0; p < 8; p++) {
            int key = p * 32 + (tid >> 3);
            int c4  = (tid & 7) * 4;
            float4 v = *(const float4*)&Xg[(long)key * DM + s * 32 + c4];
            *(__nv_bfloat162*)&Xs[key][c4]     = __float22bfloat162_rn(make_float2(v.x, v.y));
            *(__nv_bfloat162*)&Xs[key][c4 + 2] = __float22bfloat162_rn(make_float2(v.z, v.w));
        }
        // stage A slab: 64 rows x 32 halfs (already bf16)
        {
            int row = tid >> 2;
            int c   = (tid & 3) * 8;
            uint4 v = *(const uint4*)&Ag[(long)row * DM + s * 32 + c];
            *(uint4*)&Avs[row][c] = v;
        }
        __syncthreads();

        #pragma unroll
        for (int kt = 0; kt < 2; kt++) {
            unsigned afr[4][4], bfr[4][2];
            #pragma unroll
            for (int m = 0; m < 4; m++) {
                unsigned addr = (unsigned)__cvta_generic_to_shared(
                    &Avs[m * 16 + (lane & 15)][kt * 16 + (lane >> 4) * 8]);
                asm volatile("ldmatrix.sync.aligned.m8n8.x4.shared.b16 {%0,%1,%2,%3}, [%4];"
                    : "=r"(afr[m][0]), "=r"(afr[m][1]), "=r"(afr[m][2]), "=r"(afr[m][3])
                    : "r"(addr));
            }
            #pragma unroll
            for (int n = 0; n < 4; n++) {
                int l8 = lane & 15;
                unsigned addr = (unsigned)__cvta_generic_to_shared(
                    &Xs[w * 32 + n * 8 + (l8 & 7)][kt * 16 + (l8 >> 3) * 8]);
                asm volatile("ldmatrix.sync.aligned.m8n8.x2.shared.b16 {%0,%1}, [%2];"
                    : "=r"(bfr[n][0]), "=r"(bfr[n][1]) : "r"(addr));
            }
            #pragma unroll
            for (int m = 0; m < 4; m++)
                #pragma unroll
                for (int n = 0; n < 4; n++)
                    asm volatile(
                        "mma.sync.aligned.m16n8k16.row.col.f32.bf16.bf16.f32 "
                        "{%0,%1,%2,%3}, {%4,%5,%6,%7}, {%8,%9}, {%0,%1,%2,%3};"
                        : "+f"(acc[m][n][0]), "+f"(acc[m][n][1]),
                          "+f"(acc[m][n][2]), "+f"(acc[m][n][3])
                        : "r"(afr[m][0]), "r"(afr[m][1]), "r"(afr[m][2]), "r"(afr[m][3]),
                          "r"(bfr[n][0]), "r"(bfr[n][1]));
        }
        __syncthreads();
    }

    // epilogue: write S + per-row max
    float* Sbase = g_S + (long)(b * BQ) * LKV + ch * CKEYS;
    const int qr = lane >> 2;         // 0..7
    const int c2 = (lane & 3) * 2;
    #pragma unroll
    for (int m = 0; m < 4; m++) {
        float m0 = -3.0e38f, m1 = -3.0e38f;
        #pragma unroll
        for (int n = 0; n < 4; n++) {
            int col = w * 32 + n * 8 + c2;
            *(float2*)&Sbase[(long)(m * 16 + qr)     * LKV + col] = make_float2(acc[m][n][0], acc[m][n][1]);
            *(float2*)&Sbase[(long)(m * 16 + qr + 8) * LKV + col] = make_float2(acc[m][n][2], acc[m][n][3]);
            m0 = fmaxf(m0, fmaxf(acc[m][n][0], acc[m][n][1]));
            m1 = fmaxf(m1, fmaxf(acc[m][n][2], acc[m][n][3]));
        }
        #pragma unroll
        for (int o = 1; o < 4; o <<= 1) {
            m0 = fmaxf(m0, __shfl_xor_sync(0xffffffffu, m0, o));
            m1 = fmaxf(m1, __shfl_xor_sync(0xffffffffu, m1, o));
        }
        if ((lane & 3) == 0) {
            atomicMax(&red[m * 16 + qr],     f2key(m0));
            atomicMax(&red[m * 16 + qr + 8], f2key(m1));
        }
    }
    __syncthreads();
    if (tid < 64) atomicMax(&g_M[b * BQ + tid], red[tid]);
}

// ---------------------------------------------------------------------------
// Select + exact rescore + softmax + weighted-x2 accumulation, 1 warp per row.
// Candidates: bf16 score > m_bf16 - 22 (expected ~2/row). Exact fp32 scores
// for candidates, exact max over them, p = exp(s - m_e). Y accumulated in
// registers, pre-divided by Z. No atomics.
// ---------------------------------------------------------------------------
__global__ void k_select(const float* __restrict__ x2)
{
    __shared__ int   candk[8][MAXC];
    __shared__ float cands[8][MAXC];
    const int w    = threadIdx.x >> 5;
    const int lane = threadIdx.x & 31;
    const int r    = blockIdx.x * 8 + w;
    const int b    = r / BQ;
    const float th = key2f(g_M[r]) - 22.0f;

    const float4* Srow = (const float4*)(g_S + (long)r * LKV);
    int cnt = 0;
    for (int it = 0; it < 32; it++) {
        float4 v = Srow[it * 32 + lane];
        #pragma unroll
        for (int c = 0; c < 4; c++) {
            float sv = (c == 0) ? v.x : (c == 1) ? v.y : (c == 2) ? v.z : v.w;
            bool sel = sv > th;
            unsigned msk = __ballot_sync(0xffffffffu, sel);
            if (sel) {
                int pos = cnt + __popc(msk & ((1u << lane) - 1u));
                if (pos < MAXC) candk[w][pos] = (it * 32 + lane) * 4 + c;
            }
            cnt = min(cnt + __popc(msk), MAXC);
        }
    }
    __syncwarp();

    const float* Arow = g_A + (long)r * DM;
    float a[16];
    #pragma unroll
    for (int i = 0; i < 16; i++) a[i] = Arow[i * 32 + lane];

    // pass 1: exact fp32 scores + exact max over candidates
    float me = -3.0e38f;
    for (int j = 0; j < cnt; j++) {
        const float* xr = x2 + ((long)b * LKV + candk[w][j]) * DM;
        float s = 0.0f;
        #pragma unroll
        for (int i = 0; i < 16; i++) s += a[i] * xr[i * 32 + lane];
        #pragma unroll
        for (int o = 16; o > 0; o >>= 1) s += __shfl_xor_sync(0xffffffffu, s, o);
        if (lane == 0) cands[w][j] = s;
        me = fmaxf(me, s);
    }
    __syncwarp();

    // pass 2: softmax weights + register Y accumulation
    float y[16];
    #pragma unroll
    for (int i = 0; i < 16; i++) y[i] = 0.0f;
    float z = 0.0f;
    for (int j = 0; j < cnt; j++) {
        float p = expf(cands[w][j] - me);
        z += p;
        const float* xr = x2 + ((long)b * LKV + candk[w][j]) * DM;
        #pragma unroll
        for (int i = 0; i < 16; i++) y[i] += p * xr[i * 32 + lane];
    }
    float inv = 1.0f / z;
    float* Yrow = g_Y + (long)r * DM;
    #pragma unroll
    for (int i = 0; i < 16; i++) Yrow[i * 32 + lane] = y[i] * inv;
}

// ---------------------------------------------------------------------------
extern "C" void kernel_launch(void* const* d_in, const int* in_sizes, int n_in,
                              void* d_out, int out_size)
{
    const float* x1 = (const float*)d_in[0];
    const float* x2 = (const float*)d_in[1];
    // d_in[2] = mask : unused in reference forward
    const float* wq = (const float*)d_in[3];
    const float* bq = (const float*)d_in[4];
    const float* wk = (const float*)d_in[5];
    // d_in[6] = bk : cancels in softmax (per-row constant)
    const float* wv = (const float*)d_in[7];
    const float* bv = (const float*)d_in[8];
    float* out = (float*)d_out;

    k_init<<<4, 512>>>();

    // Q = x1 * wq^T + bq
    k_gemm_nt<0><<<dim3(32, 8), 256>>>(x1, wq, bq, nullptr);

    // A = sqrt(d) * Q * wk  (+ bf16 copy)
    k_gemm_nn_scale<<<dim3(32, 8), 256>>>(wk);

    // bf16 tensor-core scores + row maxima
    k_scores_tc<<<dim3(NB, NCHUNK), 256>>>(x2);

    // candidate select + exact softmax + Y (pre-divided by Z)
    k_select<<<NROWS / 8, 256>>>(x2);

    // out = Y * wv^T + bv
    k_gemm_nt<1><<<dim3(32, 8), 256>>>(nullptr, wv, bv, out);
}

// round 5
// speedup vs baseline: 7.2994x; 1.4839x over previous
#include <cuda_runtime.h>
#include <cuda_bf16.h>

#define DM 512
#define BQ 64
#define LKV 4096
#define NB 32
#define NROWS (NB * BQ)            // 2048
#define SQRT_D 22.62741699796952f
#define NCHUNK 16                  // key chunks per batch
#define CKEYS 256                  // keys per chunk
#define MAXC 64                    // candidate cap per row

// Scratch (device globals -- no allocation allowed)
__device__ float          g_W[DM * DM];       // M^T: Wt[d][j] = sqrt(d) * sum_e wk[e,d] wq[e,j]
__device__ float          g_a2[DM];           // sqrt(d) * bq . wk
__device__ float          g_A[NROWS * DM];
__device__ __nv_bfloat16  g_Ah[NROWS * DM];
__device__ float          g_Y[NROWS * DM];
__device__ float          g_S[NROWS * LKV];   // bf16-TC scores (fp32 accum)
__device__ unsigned       g_M[NROWS];

__device__ __forceinline__ unsigned f2key(float f) {
    unsigned b = __float_as_uint(f);
    return (b & 0x80000000u) ? ~b : (b | 0x80000000u);
}
__device__ __forceinline__ float key2f(unsigned u) {
    return (u & 0x80000000u) ? __uint_as_float(u & 0x7FFFFFFFu)
                             : __uint_as_float(~u);
}

__global__ void k_init() {
    int idx = blockIdx.x * blockDim.x + threadIdx.x;
    if (idx < NROWS) g_M[idx] = 0u;
}

// ---------------------------------------------------------------------------
// k_W: Wt[d,j] = SQRT_D * sum_e wk[e,d] * wq[e,j]   (512x512, fp32 exact)
// grid (8,8), 512 threads, each computes 2x4 outputs.
// ---------------------------------------------------------------------------
__global__ void k_W(const float* __restrict__ wq, const float* __restrict__ wk)
{
    __shared__ float Ks[32][68];
    __shared__ float Qs[32][68];
    const int d0 = blockIdx.x * 64, j0 = blockIdx.y * 64;
    const int t  = threadIdx.x;
    const int le = t >> 4, lf = (t & 15) * 4;   // load mapping
    const int rg = t >> 4, cg = t & 15;         // compute mapping: rows rg*2..+1, cols cg*4..+3

    float acc[2][4] = {};
    for (int k0 = 0; k0 < DM; k0 += 32) {
        float4 kv = *(const float4*)&wk[(long)(k0 + le) * DM + d0 + lf];
        float4 qv = *(const float4*)&wq[(long)(k0 + le) * DM + j0 + lf];
        *(float4*)&Ks[le][lf] = kv;
        *(float4*)&Qs[le][lf] = qv;
        __syncthreads();
        #pragma unroll
        for (int e = 0; e < 32; e++) {
            float a0 = Ks[e][rg*2], a1 = Ks[e][rg*2+1];
            float4 b = *(const float4*)&Qs[e][cg*4];
            acc[0][0]+=a0*b.x; acc[0][1]+=a0*b.y; acc[0][2]+=a0*b.z; acc[0][3]+=a0*b.w;
            acc[1][0]+=a1*b.x; acc[1][1]+=a1*b.y; acc[1][2]+=a1*b.z; acc[1][3]+=a1*b.w;
        }
        __syncthreads();
    }
    #pragma unroll
    for (int i = 0; i < 2; i++)
        #pragma unroll
        for (int j = 0; j < 4; j++)
            g_W[(long)(d0 + rg*2 + i) * DM + j0 + cg*4 + j] = SQRT_D * acc[i][j];
}

// a2[d] = SQRT_D * sum_e bq[e] * wk[e,d]
__global__ void k_a2(const float* __restrict__ wk, const float* __restrict__ bq)
{
    const int d = blockIdx.x * 256 + threadIdx.x;
    float a0 = 0.f, a1 = 0.f, a2s = 0.f, a3 = 0.f;
    #pragma unroll 4
    for (int e = 0; e < DM; e += 4) {
        a0 += bq[e]   * wk[(long)e * DM + d];
        a1 += bq[e+1] * wk[(long)(e+1) * DM + d];
        a2s+= bq[e+2] * wk[(long)(e+2) * DM + d];
        a3 += bq[e+3] * wk[(long)(e+3) * DM + d];
    }
    g_a2[d] = SQRT_D * ((a0 + a1) + (a2s + a3));
}

// ---------------------------------------------------------------------------
// Split-bf16 tensor-core NT GEMM: C[M,N] = A[M,K] * B[N,K]^T + bias
// Operands decomposed into NSPLIT bf16 planes (hi/mid/lo); products kept:
//   NSPLIT=2: hh, hm, mh               (rel err ~2^-16)
//   NSPLIT=3: + mm, hl, lh             (rel err ~2^-23, near-fp32)
// MODE 0: A=x1, B=g_W, bias=g_a2  -> g_A (fp32) + g_Ah (bf16)
// MODE 1: A=g_Y, B=wv,  bias=bv   -> Cg (d_out)
// 64x64 tile, 256 threads (8 warps: 2 m-groups x 4 n-groups, each m32xn16).
// ---------------------------------------------------------------------------
template <int NSPLIT, int MODE>
__global__ void k_split_nt(const float* __restrict__ Ag,
                           const float* __restrict__ Bg,
                           const float* __restrict__ biasg,
                           float* __restrict__ Cg)
{
    __shared__ __nv_bfloat16 As[NSPLIT][64][40];
    __shared__ __nv_bfloat16 Bs[NSPLIT][64][40];
    const int m0 = blockIdx.x * 64, n0 = blockIdx.y * 64;
    const int t = threadIdx.x, w = t >> 5, lane = t & 31;
    const int mg = w >> 2, ng = w & 3;

    const float* Asrc = (MODE == 0) ? Ag : (const float*)g_Y;
    const float* Bsrc = (MODE == 0) ? (const float*)g_W : Bg;
    const float* bias = (MODE == 0) ? (const float*)g_a2 : biasg;

    float acc[2][2][4] = {};

    for (int k0 = 0; k0 < DM; k0 += 32) {
        // stage + split both 64x32 tiles
        #pragma unroll
        for (int p = 0; p < 2; p++) {
            const int row = p * 32 + (t >> 3);
            const int c4  = (t & 7) * 4;
            float4 va = *(const float4*)&Asrc[(long)(m0 + row) * DM + k0 + c4];
            float4 vb = *(const float4*)&Bsrc[(long)(n0 + row) * DM + k0 + c4];
            float ea[4] = {va.x, va.y, va.z, va.w};
            float eb[4] = {vb.x, vb.y, vb.z, vb.w};
            #pragma unroll
            for (int c = 0; c < 4; c++) {
                float x = ea[c];
                #pragma unroll
                for (int s = 0; s < NSPLIT; s++) {
                    __nv_bfloat16 h = __float2bfloat16_rn(x);
                    As[s][row][c4 + c] = h;
                    x -= __bfloat162float(h);
                }
                x = eb[c];
                #pragma unroll
                for (int s = 0; s < NSPLIT; s++) {
                    __nv_bfloat16 h = __float2bfloat16_rn(x);
                    Bs[s][row][c4 + c] = h;
                    x -= __bfloat162float(h);
                }
            }
        }
        __syncthreads();

        #pragma unroll
        for (int kt = 0; kt < 2; kt++) {
            unsigned af[NSPLIT][2][4], bf[NSPLIT][2][2];
            #pragma unroll
            for (int s = 0; s < NSPLIT; s++) {
                #pragma unroll
                for (int mf = 0; mf < 2; mf++) {
                    unsigned addr = (unsigned)__cvta_generic_to_shared(
                        &As[s][mg*32 + mf*16 + (lane & 15)][kt*16 + (lane >> 4) * 8]);
                    asm volatile("ldmatrix.sync.aligned.m8n8.x4.shared.b16 {%0,%1,%2,%3}, [%4];"
                        : "=r"(af[s][mf][0]), "=r"(af[s][mf][1]),
                          "=r"(af[s][mf][2]), "=r"(af[s][mf][3]) : "r"(addr));
                }
                #pragma unroll
                for (int nf = 0; nf < 2; nf++) {
                    int l8 = lane & 15;
                    unsigned addr = (unsigned)__cvta_generic_to_shared(
                        &Bs[s][ng*16 + nf*8 + (l8 & 7)][kt*16 + (l8 >> 3) * 8]);
                    asm volatile("ldmatrix.sync.aligned.m8n8.x2.shared.b16 {%0,%1}, [%2];"
                        : "=r"(bf[s][nf][0]), "=r"(bf[s][nf][1]) : "r"(addr));
                }
            }
            constexpr int NC = (NSPLIT == 2) ? 3 : 6;
            const int csa[6] = {0, 0, 1, 1, 0, 2};
            const int csb[6] = {0, 1, 0, 1, 2, 0};
            #pragma unroll
            for (int c = 0; c < NC; c++) {
                const int sa = csa[c], sb = csb[c];
                #pragma unroll
                for (int mf = 0; mf < 2; mf++)
                    #pragma unroll
                    for (int nf = 0; nf < 2; nf++)
                        asm volatile(
                            "mma.sync.aligned.m16n8k16.row.col.f32.bf16.bf16.f32 "
                            "{%0,%1,%2,%3}, {%4,%5,%6,%7}, {%8,%9}, {%0,%1,%2,%3};"
                            : "+f"(acc[mf][nf][0]), "+f"(acc[mf][nf][1]),
                              "+f"(acc[mf][nf][2]), "+f"(acc[mf][nf][3])
                            : "r"(af[sa][mf][0]), "r"(af[sa][mf][1]),
                              "r"(af[sa][mf][2]), "r"(af[sa][mf][3]),
                              "r"(bf[sb][nf][0]), "r"(bf[sb][nf][1]));
            }
        }
        __syncthreads();
    }

    // epilogue
    const int qr = lane >> 2, c2 = (lane & 3) * 2;
    #pragma unroll
    for (int mf = 0; mf < 2; mf++)
        #pragma unroll
        for (int nf = 0; nf < 2; nf++) {
            const int row = m0 + mg*32 + mf*16 + qr;
            const int col = n0 + ng*16 + nf*8 + c2;
            const float b0 = bias[col], b1 = bias[col + 1];
            float v00 = acc[mf][nf][0] + b0, v01 = acc[mf][nf][1] + b1;
            float v10 = acc[mf][nf][2] + b0, v11 = acc[mf][nf][3] + b1;
            if (MODE == 0) {
                *(float2*)&g_A[(long)row * DM + col]       = make_float2(v00, v01);
                *(float2*)&g_A[(long)(row + 8) * DM + col] = make_float2(v10, v11);
                *(__nv_bfloat162*)&g_Ah[(long)row * DM + col] =
                    __float22bfloat162_rn(make_float2(v00, v01));
                *(__nv_bfloat162*)&g_Ah[(long)(row + 8) * DM + col] =
                    __float22bfloat162_rn(make_float2(v10, v11));
            } else {
                *(float2*)&Cg[(long)row * DM + col]       = make_float2(v00, v01);
                *(float2*)&Cg[(long)(row + 8) * DM + col] = make_float2(v10, v11);
            }
        }
}

// ---------------------------------------------------------------------------
// Tensor-core score pass (unchanged from round 4): S = Ah . x2h^T per batch,
// fp32 accum, plus per-row bf16-score maxima.
// ---------------------------------------------------------------------------
__global__ void k_scores_tc(const float* __restrict__ x2)
{
    __shared__ __nv_bfloat16 Xs[CKEYS][40];
    __shared__ __nv_bfloat16 Avs[64][40];
    __shared__ unsigned red[64];

    const int b   = blockIdx.x;
    const int ch  = blockIdx.y;
    const int tid = threadIdx.x;
    const int w   = tid >> 5, lane = tid & 31;

    if (tid < 64) red[tid] = 0u;

    float acc[4][4][4];
    #pragma unroll
    for (int m = 0; m < 4; m++)
        #pragma unroll
        for (int n = 0; n < 4; n++)
            #pragma unroll
            for (int c = 0; c < 4; c++) acc[m][n][c] = 0.0f;

    const float* Xg = x2 + ((long)b * LKV + (long)ch * CKEYS) * DM;
    const __nv_bfloat16* Ag = g_Ah + (long)b * BQ * DM;

    for (int s = 0; s < 16; s++) {
        #pragma unroll
        for (int p = 0; p < 8; p++) {
            int key = p * 32 + (tid >> 3);
            int c4  = (tid & 7) * 4;
            float4 v = *(const float4*)&Xg[(long)key * DM + s * 32 + c4];
            *(__nv_bfloat162*)&Xs[key][c4]     = __float22bfloat162_rn(make_float2(v.x, v.y));
            *(__nv_bfloat162*)&Xs[key][c4 + 2] = __float22bfloat162_rn(make_float2(v.z, v.w));
        }
        {
            int row = tid >> 2;
            int c   = (tid & 3) * 8;
            uint4 v = *(const uint4*)&Ag[(long)row * DM + s * 32 + c];
            *(uint4*)&Avs[row][c] = v;
        }
        __syncthreads();

        #pragma unroll
        for (int kt = 0; kt < 2; kt++) {
            unsigned afr[4][4], bfr[4][2];
            #pragma unroll
            for (int m = 0; m < 4; m++) {
                unsigned addr = (unsigned)__cvta_generic_to_shared(
                    &Avs[m * 16 + (lane & 15)][kt * 16 + (lane >> 4) * 8]);
                asm volatile("ldmatrix.sync.aligned.m8n8.x4.shared.b16 {%0,%1,%2,%3}, [%4];"
                    : "=r"(afr[m][0]), "=r"(afr[m][1]), "=r"(afr[m][2]), "=r"(afr[m][3])
                    : "r"(addr));
            }
            #pragma unroll
            for (int n = 0; n < 4; n++) {
                int l8 = lane & 15;
                unsigned addr = (unsigned)__cvta_generic_to_shared(
                    &Xs[w * 32 + n * 8 + (l8 & 7)][kt * 16 + (l8 >> 3) * 8]);
                asm volatile("ldmatrix.sync.aligned.m8n8.x2.shared.b16 {%0,%1}, [%2];"
                    : "=r"(bfr[n][0]), "=r"(bfr[n][1]) : "r"(addr));
            }
            #pragma unroll
            for (int m = 0; m < 4; m++)
                #pragma unroll
                for (int n = 0; n < 4; n++)
                    asm volatile(
                        "mma.sync.aligned.m16n8k16.row.col.f32.bf16.bf16.f32 "
                        "{%0,%1,%2,%3}, {%4,%5,%6,%7}, {%8,%9}, {%0,%1,%2,%3};"
                        : "+f"(acc[m][n][0]), "+f"(acc[m][n][1]),
                          "+f"(acc[m][n][2]), "+f"(acc[m][n][3])
                        : "r"(afr[m][0]), "r"(afr[m][1]), "r"(afr[m][2]), "r"(afr[m][3]),
                          "r"(bfr[n][0]), "r"(bfr[n][1]));
        }
        __syncthreads();
    }

    float* Sbase = g_S + (long)(b * BQ) * LKV + ch * CKEYS;
    const int qr = lane >> 2;
    const int c2 = (lane & 3) * 2;
    #pragma unroll
    for (int m = 0; m < 4; m++) {
        float m0 = -3.0e38f, m1 = -3.0e38f;
        #pragma unroll
        for (int n = 0; n < 4; n++) {
            int col = w * 32 + n * 8 + c2;
            *(float2*)&Sbase[(long)(m * 16 + qr)     * LKV + col] = make_float2(acc[m][n][0], acc[m][n][1]);
            *(float2*)&Sbase[(long)(m * 16 + qr + 8) * LKV + col] = make_float2(acc[m][n][2], acc[m][n][3]);
            m0 = fmaxf(m0, fmaxf(acc[m][n][0], acc[m][n][1]));
            m1 = fmaxf(m1, fmaxf(acc[m][n][2], acc[m][n][3]));
        }
        #pragma unroll
        for (int o = 1; o < 4; o <<= 1) {
            m0 = fmaxf(m0, __shfl_xor_sync(0xffffffffu, m0, o));
            m1 = fmaxf(m1, __shfl_xor_sync(0xffffffffu, m1, o));
        }
        if ((lane & 3) == 0) {
            atomicMax(&red[m * 16 + qr],     f2key(m0));
            atomicMax(&red[m * 16 + qr + 8], f2key(m1));
        }
    }
    __syncthreads();
    if (tid < 64) atomicMax(&g_M[b * BQ + tid], red[tid]);
}

// ---------------------------------------------------------------------------
// Select + exact fp32 rescore + softmax + weighted-x2 accumulation (unchanged).
// ---------------------------------------------------------------------------
__global__ void k_select(const float* __restrict__ x2)
{
    __shared__ int   candk[8][MAXC];
    __shared__ float cands[8][MAXC];
    const int w    = threadIdx.x >> 5;
    const int lane = threadIdx.x & 31;
    const int r    = blockIdx.x * 8 + w;
    const int b    = r / BQ;
    const float th = key2f(g_M[r]) - 22.0f;

    const float4* Srow = (const float4*)(g_S + (long)r * LKV);
    int cnt = 0;
    for (int it = 0; it < 32; it++) {
        float4 v = Srow[it * 32 + lane];
        #pragma unroll
        for (int c = 0; c < 4; c++) {
            float sv = (c == 0) ? v.x : (c == 1) ? v.y : (c == 2) ? v.z : v.w;
            bool sel = sv > th;
            unsigned msk = __ballot_sync(0xffffffffu, sel);
            if (sel) {
                int pos = cnt + __popc(msk & ((1u << lane) - 1u));
                if (pos < MAXC) candk[w][pos] = (it * 32 + lane) * 4 + c;
            }
            cnt = min(cnt + __popc(msk), MAXC);
        }
    }
    __syncwarp();

    const float* Arow = g_A + (long)r * DM;
    float a[16];
    #pragma unroll
    for (int i = 0; i < 16; i++) a[i] = Arow[i * 32 + lane];

    float me = -3.0e38f;
    for (int j = 0; j < cnt; j++) {
        const float* xr = x2 + ((long)b * LKV + candk[w][j]) * DM;
        float s = 0.0f;
        #pragma unroll
        for (int i = 0; i < 16; i++) s += a[i] * xr[i * 32 + lane];
        #pragma unroll
        for (int o = 16; o > 0; o >>= 1) s += __shfl_xor_sync(0xffffffffu, s, o);
        if (lane == 0) cands[w][j] = s;
        me = fmaxf(me, s);
    }
    __syncwarp();

    float y[16];
    #pragma unroll
    for (int i = 0; i < 16; i++) y[i] = 0.0f;
    float z = 0.0f;
    for (int j = 0; j < cnt; j++) {
        float p = expf(cands[w][j] - me);
        z += p;
        const float* xr = x2 + ((long)b * LKV + candk[w][j]) * DM;
        #pragma unroll
        for (int i = 0; i < 16; i++) y[i] += p * xr[i * 32 + lane];
    }
    float inv = 1.0f / z;
    float* Yrow = g_Y + (long)r * DM;
    #pragma unroll
    for (int i = 0; i < 16; i++) Yrow[i * 32 + lane] = y[i] * inv;
}

// ---------------------------------------------------------------------------
extern "C" void kernel_launch(void* const* d_in, const int* in_sizes, int n_in,
                              void* d_out, int out_size)
{
    const float* x1 = (const float*)d_in[0];
    const float* x2 = (const float*)d_in[1];
    // d_in[2] = mask : unused in reference forward
    const float* wq = (const float*)d_in[3];
    const float* bq = (const float*)d_in[4];
    const float* wk = (const float*)d_in[5];
    // d_in[6] = bk : cancels in softmax (per-row constant)
    const float* wv = (const float*)d_in[7];
    const float* bv = (const float*)d_in[8];
    float* out = (float*)d_out;

    k_init<<<4, 512>>>();

    // Wt = sqrt(d) * wk^T * wq ; a2 = sqrt(d) * bq . wk
    k_W<<<dim3(8, 8), 512>>>(wq, wk);
    k_a2<<<2, 256>>>(wk, bq);

    // A = x1 * Wt^T + a2  (3-split bf16 TC, near-fp32), emits g_A + g_Ah
    k_split_nt<3, 0><<<dim3(32, 8), 256>>>(x1, nullptr, nullptr, nullptr);

    // bf16 tensor-core scores + row maxima
    k_scores_tc<<<dim3(NB, NCHUNK), 256>>>(x2);

    // candidate select + exact softmax + Y (pre-divided by Z)
    k_select<<<NROWS / 8, 256>>>(x2);

    // out = Y * wv^T + bv  (2-split bf16 TC)
    k_split_nt<2, 1><<<dim3(32, 8), 256>>>(nullptr, wv, bv, out);
}

// round 8
// speedup vs baseline: 7.6830x; 1.0525x over previous
#include <cuda_runtime.h>
#include <cuda_bf16.h>

#define DM 512
#define BQ 64
#define LKV 4096
#define NB 32
#define NROWS (NB * BQ)            // 2048
#define SQRT_D 22.62741699796952f
#define NCHUNK 16
#define CKEYS 256
#define MAXC 64

// Scratch (device globals -- no allocation allowed)
__device__ __nv_bfloat16  g_x1h[3][NROWS * DM];   // x1 split planes
__device__ __nv_bfloat16  g_Wh[3][DM * DM];       // Wt split planes
__device__ __nv_bfloat16  g_Yh[2][NROWS * DM];    // Y/Z split planes (from select)
__device__ __nv_bfloat16  g_wvh[2][DM * DM];      // wv split planes
__device__ float          g_a2[DM];               // sqrt(d) * bq . wk
__device__ float          g_A[NROWS * DM];
__device__ __nv_bfloat16  g_Ah[NROWS * DM];
__device__ __nv_bfloat16  g_Sh[(long)NROWS * LKV]; // bf16 scores (16.7 MB)
__device__ unsigned       g_M[NROWS];

__device__ __forceinline__ unsigned f2key(float f) {
    unsigned b = __float_as_uint(f);
    return (b & 0x80000000u) ? ~b : (b | 0x80000000u);
}
__device__ __forceinline__ float key2f(unsigned u) {
    return (u & 0x80000000u) ? __uint_as_float(u & 0x7FFFFFFFu)
                             : __uint_as_float(~u);
}
__device__ __forceinline__ __nv_bfloat162 bf2(__nv_bfloat16 a, __nv_bfloat16 b) {
    __nv_bfloat162 t; t.x = a; t.y = b; return t;
}

__global__ void k_init() {
    int idx = blockIdx.x * blockDim.x + threadIdx.x;
    if (idx < NROWS) g_M[idx] = 0u;
}

// ---------------------------------------------------------------------------
// Split a fp32 matrix into NS bf16 planes. TGT 0: x1 -> g_x1h ; 1: wv -> g_wvh
// One float4 group per thread.
// ---------------------------------------------------------------------------
template <int NS, int TGT>
__global__ void k_prep(const float* __restrict__ src)
{
    const int i = blockIdx.x * blockDim.x + threadIdx.x;
    float4 v = ((const float4*)src)[i];
    float e[4] = {v.x, v.y, v.z, v.w};
    __nv_bfloat16 h[3][4];
    #pragma unroll
    for (int c = 0; c < 4; c++) {
        float x = e[c];
        #pragma unroll
        for (int s = 0; s < NS; s++) {
            h[s][c] = __float2bfloat16_rn(x);
            x -= __bfloat162float(h[s][c]);
        }
    }
    #pragma unroll
    for (int s = 0; s < NS; s++) {
        __nv_bfloat16* p = (TGT == 0) ? g_x1h[s] : g_wvh[s];
        ((__nv_bfloat162*)p)[i * 2]     = bf2(h[s][0], h[s][1]);
        ((__nv_bfloat162*)p)[i * 2 + 1] = bf2(h[s][2], h[s][3]);
    }
}

// ---------------------------------------------------------------------------
// k_W: Wt[n,k] = SQRT_D * sum_e wk[e,n] * wq[e,k]  (512x512), emits 3 bf16 planes
// ---------------------------------------------------------------------------
__global__ void k_W(const float* __restrict__ wq, const float* __restrict__ wk)
{
    __shared__ float Ks[32][68];
    __shared__ float Qs[32][68];
    const int d0 = blockIdx.x * 64, j0 = blockIdx.y * 64;
    const int t  = threadIdx.x;
    const int le = t >> 4, lf = (t & 15) * 4;
    const int rg = t >> 4, cg = t & 15;

    float acc[2][4] = {};
    for (int k0 = 0; k0 < DM; k0 += 32) {
        *(float4*)&Ks[le][lf] = *(const float4*)&wk[(long)(k0 + le) * DM + d0 + lf];
        *(float4*)&Qs[le][lf] = *(const float4*)&wq[(long)(k0 + le) * DM + j0 + lf];
        __syncthreads();
        #pragma unroll
        for (int e = 0; e < 32; e++) {
            float a0 = Ks[e][rg*2], a1 = Ks[e][rg*2+1];
            float4 b = *(const float4*)&Qs[e][cg*4];
            acc[0][0]+=a0*b.x; acc[0][1]+=a0*b.y; acc[0][2]+=a0*b.z; acc[0][3]+=a0*b.w;
            acc[1][0]+=a1*b.x; acc[1][1]+=a1*b.y; acc[1][2]+=a1*b.z; acc[1][3]+=a1*b.w;
        }
        __syncthreads();
    }
    #pragma unroll
    for (int i = 0; i < 2; i++)
        #pragma unroll
        for (int j = 0; j < 4; j++) {
            float v = SQRT_D * acc[i][j];
            long idx = (long)(d0 + rg*2 + i) * DM + j0 + cg*4 + j;
            #pragma unroll
            for (int s = 0; s < 3; s++) {
                __nv_bfloat16 h = __float2bfloat16_rn(v);
                g_Wh[s][idx] = h;
                v -= __bfloat162float(h);
            }
        }
}

// a2[d] = SQRT_D * sum_e bq[e] * wk[e,d]
__global__ void k_a2(const float* __restrict__ wk, const float* __restrict__ bq)
{
    const int d = blockIdx.x * 256 + threadIdx.x;
    float a0 = 0.f, a1 = 0.f, a2s = 0.f, a3 = 0.f;
    #pragma unroll 4
    for (int e = 0; e < DM; e += 4) {
        a0 += bq[e]   * wk[(long)e * DM + d];
        a1 += bq[e+1] * wk[(long)(e+1) * DM + d];
        a2s+= bq[e+2] * wk[(long)(e+2) * DM + d];
        a3 += bq[e+3] * wk[(long)(e+3) * DM + d];
    }
    g_a2[d] = SQRT_D * ((a0 + a1) + (a2s + a3));
}

// ---------------------------------------------------------------------------
// Lean plane-fed split-bf16 TC NT GEMM: C[M,N] = sum planes A_s * B_t^T + bias
// MODE 0: A=g_x1h(3), B=g_Wh(3), NC=6, bias=g_a2 -> g_A + g_Ah
// MODE 1: A=g_Yh(2),  B=g_wvh(2), NC=3, bias=bv  -> Cg
// 64x64 tile, 256 threads (8 warps: 2 m-groups x 4 n-groups).
// ---------------------------------------------------------------------------
template <int NS, int NC, int MODE>
__global__ void k_tc_nt(const float* __restrict__ biasg, float* __restrict__ Cg)
{
    __shared__ __nv_bfloat16 As[NS][64][40];
    __shared__ __nv_bfloat16 Bs[NS][64][40];
    const int m0 = blockIdx.x * 64, n0 = blockIdx.y * 64;
    const int t = threadIdx.x, w = t >> 5, lane = t & 31;
    const int mg = w >> 2, ng = w & 3;
    const float* bias = (MODE == 0) ? (const float*)g_a2 : biasg;

    float acc[2][2][4] = {};
    const int srow = t >> 2, sc8 = (t & 3) * 8;

    for (int k0 = 0; k0 < DM; k0 += 32) {
        #pragma unroll
        for (int s = 0; s < NS; s++) {
            const __nv_bfloat16* Ap = (MODE == 0) ? g_x1h[s] : g_Yh[s];
            const __nv_bfloat16* Bp = (MODE == 0) ? g_Wh[s]  : g_wvh[s];
            *(uint4*)&As[s][srow][sc8] = *(const uint4*)&Ap[(long)(m0 + srow) * DM + k0 + sc8];
            *(uint4*)&Bs[s][srow][sc8] = *(const uint4*)&Bp[(long)(n0 + srow) * DM + k0 + sc8];
        }
        __syncthreads();

        #pragma unroll
        for (int kt = 0; kt < 2; kt++) {
            unsigned af[NS][2][4], bf[NS][2][2];
            #pragma unroll
            for (int s = 0; s < NS; s++) {
                #pragma unroll
                for (int mf = 0; mf < 2; mf++) {
                    unsigned addr = (unsigned)__cvta_generic_to_shared(
                        &As[s][mg*32 + mf*16 + (lane & 15)][kt*16 + (lane >> 4) * 8]);
                    asm volatile("ldmatrix.sync.aligned.m8n8.x4.shared.b16 {%0,%1,%2,%3}, [%4];"
                        : "=r"(af[s][mf][0]), "=r"(af[s][mf][1]),
                          "=r"(af[s][mf][2]), "=r"(af[s][mf][3]) : "r"(addr));
                }
                #pragma unroll
                for (int nf = 0; nf < 2; nf++) {
                    int l8 = lane & 15;
                    unsigned addr = (unsigned)__cvta_generic_to_shared(
                        &Bs[s][ng*16 + nf*8 + (l8 & 7)][kt*16 + (l8 >> 3) * 8]);
                    asm volatile("ldmatrix.sync.aligned.m8n8.x2.shared.b16 {%0,%1}, [%2];"
                        : "=r"(bf[s][nf][0]), "=r"(bf[s][nf][1]) : "r"(addr));
                }
            }
            const int csa[6] = {0, 0, 1, 1, 0, 2};
            const int csb[6] = {0, 1, 0, 1, 2, 0};
            #pragma unroll
            for (int c = 0; c < NC; c++) {
                const int sa = csa[c], sb = csb[c];
                #pragma unroll
                for (int mf = 0; mf < 2; mf++)
                    #pragma unroll
                    for (int nf = 0; nf < 2; nf++)
                        asm volatile(
                            "mma.sync.aligned.m16n8k16.row.col.f32.bf16.bf16.f32 "
                            "{%0,%1,%2,%3}, {%4,%5,%6,%7}, {%8,%9}, {%0,%1,%2,%3};"
                            : "+f"(acc[mf][nf][0]), "+f"(acc[mf][nf][1]),
                              "+f"(acc[mf][nf][2]), "+f"(acc[mf][nf][3])
                            : "r"(af[sa][mf][0]), "r"(af[sa][mf][1]),
                              "r"(af[sa][mf][2]), "r"(af[sa][mf][3]),
                              "r"(bf[sb][nf][0]), "r"(bf[sb][nf][1]));
            }
        }
        __syncthreads();
    }

    const int qr = lane >> 2, c2 = (lane & 3) * 2;
    #pragma unroll
    for (int mf = 0; mf < 2; mf++)
        #pragma unroll
        for (int nf = 0; nf < 2; nf++) {
            const int row = m0 + mg*32 + mf*16 + qr;
            const int col = n0 + ng*16 + nf*8 + c2;
            const float b0 = bias[col], b1 = bias[col + 1];
            float v00 = acc[mf][nf][0] + b0, v01 = acc[mf][nf][1] + b1;
            float v10 = acc[mf][nf][2] + b0, v11 = acc[mf][nf][3] + b1;
            if (MODE == 0) {
                *(float2*)&g_A[(long)row * DM + col]       = make_float2(v00, v01);
                *(float2*)&g_A[(long)(row + 8) * DM + col] = make_float2(v10, v11);
                *(__nv_bfloat162*)&g_Ah[(long)row * DM + col] =
                    __float22bfloat162_rn(make_float2(v00, v01));
                *(__nv_bfloat162*)&g_Ah[(long)(row + 8) * DM + col] =
                    __float22bfloat162_rn(make_float2(v10, v11));
            } else {
                *(float2*)&Cg[(long)row * DM + col]       = make_float2(v00, v01);
                *(float2*)&Cg[(long)(row + 8) * DM + col] = make_float2(v10, v11);
            }
        }
}

// ---------------------------------------------------------------------------
// TC score pass: S = Ah . x2h^T (fp32 accum), stores S as bf16 + row maxima.
// ---------------------------------------------------------------------------
__global__ void k_scores_tc(const float* __restrict__ x2)
{
    __shared__ __nv_bfloat16 Xs[CKEYS][40];
    __shared__ __nv_bfloat16 Avs[64][40];
    __shared__ unsigned red[64];

    const int b   = blockIdx.x;
    const int ch  = blockIdx.y;
    const int tid = threadIdx.x;
    const int w   = tid >> 5, lane = tid & 31;

    if (tid < 64) red[tid] = 0u;

    float acc[4][4][4];
    #pragma unroll
    for (int m = 0; m < 4; m++)
        #pragma unroll
        for (int n = 0; n < 4; n++)
            #pragma unroll
            for (int c = 0; c < 4; c++) acc[m][n][c] = 0.0f;

    const float* Xg = x2 + ((long)b * LKV + (long)ch * CKEYS) * DM;
    const __nv_bfloat16* Ag = g_Ah + (long)b * BQ * DM;

    for (int s = 0; s < 16; s++) {
        #pragma unroll
        for (int p = 0; p < 8; p++) {
            int key = p * 32 + (tid >> 3);
            int c4  = (tid & 7) * 4;
            float4 v = *(const float4*)&Xg[(long)key * DM + s * 32 + c4];
            *(__nv_bfloat162*)&Xs[key][c4]     = __float22bfloat162_rn(make_float2(v.x, v.y));
            *(__nv_bfloat162*)&Xs[key][c4 + 2] = __float22bfloat162_rn(make_float2(v.z, v.w));
        }
        {
            int row = tid >> 2;
            int c   = (tid & 3) * 8;
            *(uint4*)&Avs[row][c] = *(const uint4*)&Ag[(long)row * DM + s * 32 + c];
        }
        __syncthreads();

        #pragma unroll
        for (int kt = 0; kt < 2; kt++) {
            unsigned afr[4][4], bfr[4][2];
            #pragma unroll
            for (int m = 0; m < 4; m++) {
                unsigned addr = (unsigned)__cvta_generic_to_shared(
                    &Avs[m * 16 + (lane & 15)][kt * 16 + (lane >> 4) * 8]);
                asm volatile("ldmatrix.sync.aligned.m8n8.x4.shared.b16 {%0,%1,%2,%3}, [%4];"
                    : "=r"(afr[m][0]), "=r"(afr[m][1]), "=r"(afr[m][2]), "=r"(afr[m][3])
                    : "r"(addr));
            }
            #pragma unroll
            for (int n = 0; n < 4; n++) {
                int l8 = lane & 15;
                unsigned addr = (unsigned)__cvta_generic_to_shared(
                    &Xs[w * 32 + n * 8 + (l8 & 7)][kt * 16 + (l8 >> 3) * 8]);
                asm volatile("ldmatrix.sync.aligned.m8n8.x2.shared.b16 {%0,%1}, [%2];"
                    : "=r"(bfr[n][0]), "=r"(bfr[n][1]) : "r"(addr));
            }
            #pragma unroll
            for (int m = 0; m < 4; m++)
                #pragma unroll
                for (int n = 0; n < 4; n++)
                    asm volatile(
                        "mma.sync.aligned.m16n8k16.row.col.f32.bf16.bf16.f32 "
                        "{%0,%1,%2,%3}, {%4,%5,%6,%7}, {%8,%9}, {%0,%1,%2,%3};"
                        : "+f"(acc[m][n][0]), "+f"(acc[m][n][1]),
                          "+f"(acc[m][n][2]), "+f"(acc[m][n][3])
                        : "r"(afr[m][0]), "r"(afr[m][1]), "r"(afr[m][2]), "r"(afr[m][3]),
                          "r"(bfr[n][0]), "r"(bfr[n][1]));
        }
        __syncthreads();
    }

    __nv_bfloat16* Sbase = g_Sh + (long)(b * BQ) * LKV + ch * CKEYS;
    const int qr = lane >> 2;
    const int c2 = (lane & 3) * 2;
    #pragma unroll
    for (int m = 0; m < 4; m++) {
        float m0 = -3.0e38f, m1 = -3.0e38f;
        #pragma unroll
        for (int n = 0; n < 4; n++) {
            int col = w * 32 + n * 8 + c2;
            *(__nv_bfloat162*)&Sbase[(long)(m * 16 + qr)     * LKV + col] =
                __float22bfloat162_rn(make_float2(acc[m][n][0], acc[m][n][1]));
            *(__nv_bfloat162*)&Sbase[(long)(m * 16 + qr + 8) * LKV + col] =
                __float22bfloat162_rn(make_float2(acc[m][n][2], acc[m][n][3]));
            m0 = fmaxf(m0, fmaxf(acc[m][n][0], acc[m][n][1]));
            m1 = fmaxf(m1, fmaxf(acc[m][n][2], acc[m][n][3]));
        }
        #pragma unroll
        for (int o = 1; o < 4; o <<= 1) {
            m0 = fmaxf(m0, __shfl_xor_sync(0xffffffffu, m0, o));
            m1 = fmaxf(m1, __shfl_xor_sync(0xffffffffu, m1, o));
        }
        if ((lane & 3) == 0) {
            atomicMax(&red[m * 16 + qr],     f2key(m0));
            atomicMax(&red[m * 16 + qr + 8], f2key(m1));
        }
    }
    __syncthreads();
    if (tid < 64) atomicMax(&g_M[b * BQ + tid], red[tid]);
}

// ---------------------------------------------------------------------------
// Select (bf16 S) + exact fp32 rescore + softmax + Y accumulation, emitting
// Y/Z directly as 2 bf16 split planes. 1 warp per row, no atomics.
// ---------------------------------------------------------------------------
__global__ void k_select(const float* __restrict__ x2)
{
    __shared__ int   candk[8][MAXC];
    __shared__ float cands[8][MAXC];
    const int w    = threadIdx.x >> 5;
    const int lane = threadIdx.x & 31;
    const int r    = blockIdx.x * 8 + w;
    const int b    = r / BQ;
    const float th = key2f(g_M[r]) - 23.0f;   // widened: bf16 S storage error

    const uint4* Srow = (const uint4*)(g_Sh + (long)r * LKV);
    int cnt = 0;
    for (int it = 0; it < 16; it++) {
        uint4 v = Srow[it * 32 + lane];
        unsigned wd[4] = {v.x, v.y, v.z, v.w};
        #pragma unroll
        for (int q = 0; q < 4; q++) {
            __nv_bfloat162 p2 = *(__nv_bfloat162*)&wd[q];
            float sv0 = __bfloat162float(p2.x);
            float sv1 = __bfloat162float(p2.y);
            #pragma unroll
            for (int h = 0; h < 2; h++) {
                float sv = h ? sv1 : sv0;
                bool sel = sv > th;
                unsigned msk = __ballot_sync(0xffffffffu, sel);
                if (sel) {
                    int pos = cnt + __popc(msk & ((1u << lane) - 1u));
                    if (pos < MAXC) candk[w][pos] = (it * 32 + lane) * 8 + q * 2 + h;
                }
                cnt = min(cnt + __popc(msk), MAXC);
            }
        }
    }
    __syncwarp();

    const float* Arow = g_A + (long)r * DM;
    float a[16];
    #pragma unroll
    for (int i = 0; i < 16; i++) a[i] = Arow[i * 32 + lane];

    // pass 1: exact fp32 scores + max
    float me = -3.0e38f;
    for (int j = 0; j < cnt; j++) {
        const float* xr = x2 + ((long)b * LKV + candk[w][j]) * DM;
        float s = 0.0f;
        #pragma unroll
        for (int i = 0; i < 16; i++) s += a[i] * xr[i * 32 + lane];
        #pragma unroll
        for (int o = 16; o > 0; o >>= 1) s += __shfl_xor_sync(0xffffffffu, s, o);
        if (lane == 0) cands[w][j] = s;
        me = fmaxf(me, s);
    }
    __syncwarp();

    // pass 2: softmax weights + register Y accumulation
    float y[16];
    #pragma unroll
    for (int i = 0; i < 16; i++) y[i] = 0.0f;
    float z = 0.0f;
    for (int j = 0; j < cnt; j++) {
        float p = expf(cands[w][j] - me);
        z += p;
        const float* xr = x2 + ((long)b * LKV + candk[w][j]) * DM;
        #pragma unroll
        for (int i = 0; i < 16; i++) y[i] += p * xr[i * 32 + lane];
    }
    float inv = 1.0f / z;
    #pragma unroll
    for (int i = 0; i < 16; i++) {
        float v = y[i] * inv;
        __nv_bfloat16 h0 = __float2bfloat16_rn(v);
        __nv_bfloat16 h1 = __float2bfloat16_rn(v - __bfloat162float(h0));
        g_Yh[0][(long)r * DM + i * 32 + lane] = h0;
        g_Yh[1][(long)r * DM + i * 32 + lane] = h1;
    }
}

// ---------------------------------------------------------------------------
extern "C" void kernel_launch(void* const* d_in, const int* in_sizes, int n_in,
                              void* d_out, int out_size)
{
    const float* x1 = (const float*)d_in[0];
    const float* x2 = (const float*)d_in[1];
    // d_in[2] = mask : unused in reference forward
    const float* wq = (const float*)d_in[3];
    const float* bq = (const float*)d_in[4];
    const float* wk = (const float*)d_in[5];
    // d_in[6] = bk : cancels in softmax (per-row constant)
    const float* wv = (const float*)d_in[7];
    const float* bv = (const float*)d_in[8];
    float* out = (float*)d_out;

    k_init<<<4, 512>>>();

    // parameter prep (independent, cheap)
    k_W<<<dim3(8, 8), 512>>>(wq, wk);                 // Wt planes (3)
    k_a2<<<2, 256>>>(wk, bq);                         // bias fold
    k_prep<3, 0><<<1024, 256>>>(x1);                  // x1 planes (3)
    k_prep<2, 1><<<256, 256>>>(wv);                   // wv planes (2)

    // A = x1 * Wt^T + a2  (3-split plane TC) -> g_A + g_Ah
    k_tc_nt<3, 6, 0><<<dim3(32, 8), 256>>>(nullptr, nullptr);

    // bf16 TC scores (stored bf16) + row maxima
    k_scores_tc<<<dim3(NB, NCHUNK), 256>>>(x2);

    // select + exact softmax + Y planes (2)
    k_select<<<NROWS / 8, 256>>>(x2);

    // out = Y * wv^T + bv  (2-split plane TC)
    k_tc_nt<2, 3, 1><<<dim3(32, 8), 256>>>(bv, out);
}

// round 11
// speedup vs baseline: 8.1562x; 1.0616x over previous
#include <cuda_runtime.h>
#include <cuda_bf16.h>

#define DM 512
#define BQ 64
#define LKV 4096
#define NB 32
#define NROWS (NB * BQ)            // 2048
#define SQRT_D 22.62741699796952f
#define NCHUNK 16
#define CKEYS 256
#define MAXC 64

// Scratch (device globals -- no allocation allowed)
__device__ __nv_bfloat16  g_x1h[3][NROWS * DM];   // x1 split planes
__device__ __nv_bfloat16  g_Wh[3][DM * DM];       // Wt split planes
__device__ __nv_bfloat16  g_Yh[2][NROWS * DM];    // Y/Z split planes (from select)
__device__ __nv_bfloat16  g_wvh[2][DM * DM];      // wv split planes
__device__ float          g_a2[DM];               // sqrt(d) * bq . wk
__device__ float          g_A[NROWS * DM];
__device__ __nv_bfloat16  g_Ah[NROWS * DM];
__device__ __nv_bfloat16  g_Sh[(long)NROWS * LKV]; // bf16 scores (16.7 MB)
__device__ unsigned       g_M[NROWS];

__device__ __forceinline__ unsigned f2key(float f) {
    unsigned b = __float_as_uint(f);
    return (b & 0x80000000u) ? ~b : (b | 0x80000000u);
}
__device__ __forceinline__ float key2f(unsigned u) {
    return (u & 0x80000000u) ? __uint_as_float(u & 0x7FFFFFFFu)
                             : __uint_as_float(~u);
}
__device__ __forceinline__ __nv_bfloat162 bf2(__nv_bfloat16 a, __nv_bfloat16 b) {
    __nv_bfloat162 t; t.x = a; t.y = b; return t;
}
__device__ __forceinline__ unsigned bf2u(__nv_bfloat162 h) {
    return *(unsigned*)&h;
}

__global__ void k_init() {
    int idx = blockIdx.x * blockDim.x + threadIdx.x;
    if (idx < NROWS) g_M[idx] = 0u;
}

// ---------------------------------------------------------------------------
// Split a fp32 matrix into NS bf16 planes. TGT 0: x1 -> g_x1h ; 1: wv -> g_wvh
// ---------------------------------------------------------------------------
template <int NS, int TGT>
__global__ void k_prep(const float* __restrict__ src)
{
    const int i = blockIdx.x * blockDim.x + threadIdx.x;
    float4 v = ((const float4*)src)[i];
    float e[4] = {v.x, v.y, v.z, v.w};
    __nv_bfloat16 h[3][4];
    #pragma unroll
    for (int c = 0; c < 4; c++) {
        float x = e[c];
        #pragma unroll
        for (int s = 0; s < NS; s++) {
            h[s][c] = __float2bfloat16_rn(x);
            x -= __bfloat162float(h[s][c]);
        }
    }
    #pragma unroll
    for (int s = 0; s < NS; s++) {
        __nv_bfloat16* p = (TGT == 0) ? g_x1h[s] : g_wvh[s];
        ((__nv_bfloat162*)p)[i * 2]     = bf2(h[s][0], h[s][1]);
        ((__nv_bfloat162*)p)[i * 2 + 1] = bf2(h[s][2], h[s][3]);
    }
}

// ---------------------------------------------------------------------------
// k_W: Wt[n,k] = SQRT_D * sum_e wk[e,n] * wq[e,k]  (512x512), emits 3 bf16 planes
// ---------------------------------------------------------------------------
__global__ void k_W(const float* __restrict__ wq, const float* __restrict__ wk)
{
    __shared__ float Ks[32][68];
    __shared__ float Qs[32][68];
    const int d0 = blockIdx.x * 64, j0 = blockIdx.y * 64;
    const int t  = threadIdx.x;
    const int le = t >> 4, lf = (t & 15) * 4;
    const int rg = t >> 4, cg = t & 15;

    float acc[2][4] = {};
    for (int k0 = 0; k0 < DM; k0 += 32) {
        *(float4*)&Ks[le][lf] = *(const float4*)&wk[(long)(k0 + le) * DM + d0 + lf];
        *(float4*)&Qs[le][lf] = *(const float4*)&wq[(long)(k0 + le) * DM + j0 + lf];
        __syncthreads();
        #pragma unroll
        for (int e = 0; e < 32; e++) {
            float a0 = Ks[e][rg*2], a1 = Ks[e][rg*2+1];
            float4 b = *(const float4*)&Qs[e][cg*4];
            acc[0][0]+=a0*b.x; acc[0][1]+=a0*b.y; acc[0][2]+=a0*b.z; acc[0][3]+=a0*b.w;
            acc[1][0]+=a1*b.x; acc[1][1]+=a1*b.y; acc[1][2]+=a1*b.z; acc[1][3]+=a1*b.w;
        }
        __syncthreads();
    }
    #pragma unroll
    for (int i = 0; i < 2; i++)
        #pragma unroll
        for (int j = 0; j < 4; j++) {
            float v = SQRT_D * acc[i][j];
            long idx = (long)(d0 + rg*2 + i) * DM + j0 + cg*4 + j;
            #pragma unroll
            for (int s = 0; s < 3; s++) {
                __nv_bfloat16 h = __float2bfloat16_rn(v);
                g_Wh[s][idx] = h;
                v -= __bfloat162float(h);
            }
        }
}

// a2[d] = SQRT_D * sum_e bq[e] * wk[e,d]
__global__ void k_a2(const float* __restrict__ wk, const float* __restrict__ bq)
{
    const int d = blockIdx.x * 256 + threadIdx.x;
    float a0 = 0.f, a1 = 0.f, a2s = 0.f, a3 = 0.f;
    #pragma unroll 4
    for (int e = 0; e < DM; e += 4) {
        a0 += bq[e]   * wk[(long)e * DM + d];
        a1 += bq[e+1] * wk[(long)(e+1) * DM + d];
        a2s+= bq[e+2] * wk[(long)(e+2) * DM + d];
        a3 += bq[e+3] * wk[(long)(e+3) * DM + d];
    }
    g_a2[d] = SQRT_D * ((a0 + a1) + (a2s + a3));
}

// ---------------------------------------------------------------------------
// Plane-fed split-bf16 TC NT GEMM (unchanged from round 8).
// ---------------------------------------------------------------------------
template <int NS, int NC, int MODE>
__global__ void k_tc_nt(const float* __restrict__ biasg, float* __restrict__ Cg)
{
    __shared__ __nv_bfloat16 As[NS][64][40];
    __shared__ __nv_bfloat16 Bs[NS][64][40];
    const int m0 = blockIdx.x * 64, n0 = blockIdx.y * 64;
    const int t = threadIdx.x, w = t >> 5, lane = t & 31;
    const int mg = w >> 2, ng = w & 3;
    const float* bias = (MODE == 0) ? (const float*)g_a2 : biasg;

    float acc[2][2][4] = {};
    const int srow = t >> 2, sc8 = (t & 3) * 8;

    for (int k0 = 0; k0 < DM; k0 += 32) {
        #pragma unroll
        for (int s = 0; s < NS; s++) {
            const __nv_bfloat16* Ap = (MODE == 0) ? g_x1h[s] : g_Yh[s];
            const __nv_bfloat16* Bp = (MODE == 0) ? g_Wh[s]  : g_wvh[s];
            *(uint4*)&As[s][srow][sc8] = *(const uint4*)&Ap[(long)(m0 + srow) * DM + k0 + sc8];
            *(uint4*)&Bs[s][srow][sc8] = *(const uint4*)&Bp[(long)(n0 + srow) * DM + k0 + sc8];
        }
        __syncthreads();

        #pragma unroll
        for (int kt = 0; kt < 2; kt++) {
            unsigned af[NS][2][4], bf[NS][2][2];
            #pragma unroll
            for (int s = 0; s < NS; s++) {
                #pragma unroll
                for (int mf = 0; mf < 2; mf++) {
                    unsigned addr = (unsigned)__cvta_generic_to_shared(
                        &As[s][mg*32 + mf*16 + (lane & 15)][kt*16 + (lane >> 4) * 8]);
                    asm volatile("ldmatrix.sync.aligned.m8n8.x4.shared.b16 {%0,%1,%2,%3}, [%4];"
                        : "=r"(af[s][mf][0]), "=r"(af[s][mf][1]),
                          "=r"(af[s][mf][2]), "=r"(af[s][mf][3]) : "r"(addr));
                }
                #pragma unroll
                for (int nf = 0; nf < 2; nf++) {
                    int l8 = lane & 15;
                    unsigned addr = (unsigned)__cvta_generic_to_shared(
                        &Bs[s][ng*16 + nf*8 + (l8 & 7)][kt*16 + (l8 >> 3) * 8]);
                    asm volatile("ldmatrix.sync.aligned.m8n8.x2.shared.b16 {%0,%1}, [%2];"
                        : "=r"(bf[s][nf][0]), "=r"(bf[s][nf][1]) : "r"(addr));
                }
            }
            const int csa[6] = {0, 0, 1, 1, 0, 2};
            const int csb[6] = {0, 1, 0, 1, 2, 0};
            #pragma unroll
            for (int c = 0; c < NC; c++) {
                const int sa = csa[c], sb = csb[c];
                #pragma unroll
                for (int mf = 0; mf < 2; mf++)
                    #pragma unroll
                    for (int nf = 0; nf < 2; nf++)
                        asm volatile(
                            "mma.sync.aligned.m16n8k16.row.col.f32.bf16.bf16.f32 "
                            "{%0,%1,%2,%3}, {%4,%5,%6,%7}, {%8,%9}, {%0,%1,%2,%3};"
                            : "+f"(acc[mf][nf][0]), "+f"(acc[mf][nf][1]),
                              "+f"(acc[mf][nf][2]), "+f"(acc[mf][nf][3])
                            : "r"(af[sa][mf][0]), "r"(af[sa][mf][1]),
                              "r"(af[sa][mf][2]), "r"(af[sa][mf][3]),
                              "r"(bf[sb][nf][0]), "r"(bf[sb][nf][1]));
            }
        }
        __syncthreads();
    }

    const int qr = lane >> 2, c2 = (lane & 3) * 2;
    #pragma unroll
    for (int mf = 0; mf < 2; mf++)
        #pragma unroll
        for (int nf = 0; nf < 2; nf++) {
            const int row = m0 + mg*32 + mf*16 + qr;
            const int col = n0 + ng*16 + nf*8 + c2;
            const float b0 = bias[col], b1 = bias[col + 1];
            float v00 = acc[mf][nf][0] + b0, v01 = acc[mf][nf][1] + b1;
            float v10 = acc[mf][nf][2] + b0, v11 = acc[mf][nf][3] + b1;
            if (MODE == 0) {
                *(float2*)&g_A[(long)row * DM + col]       = make_float2(v00, v01);
                *(float2*)&g_A[(long)(row + 8) * DM + col] = make_float2(v10, v11);
                *(__nv_bfloat162*)&g_Ah[(long)row * DM + col] =
                    __float22bfloat162_rn(make_float2(v00, v01));
                *(__nv_bfloat162*)&g_Ah[(long)(row + 8) * DM + col] =
                    __float22bfloat162_rn(make_float2(v10, v11));
            } else {
                *(float2*)&Cg[(long)row * DM + col]       = make_float2(v00, v01);
                *(float2*)&Cg[(long)(row + 8) * DM + col] = make_float2(v10, v11);
            }
        }
}

// ---------------------------------------------------------------------------
// TC score pass, restructured: B fragments loaded DIRECTLY from global x2
// (float2 -> bf16x2 cvt, no smem staging, no per-stage syncs). A resident in
// smem in two half-k phases (64 x 264 halfs, conflict-free ldmatrix).
// S stored bf16 + per-row maxima.
// ---------------------------------------------------------------------------
__global__ void __launch_bounds__(256, 2) k_scores_tc(const float* __restrict__ x2)
{
    __shared__ __nv_bfloat16 Avs[64][264];   // 33.8 KB, stride 528B = 16 mod 128
    __shared__ unsigned red[64];

    const int b   = blockIdx.x;
    const int ch  = blockIdx.y;
    const int tid = threadIdx.x;
    const int w   = tid >> 5, lane = tid & 31;

    if (tid < 64) red[tid] = 0u;

    float acc[4][4][4];
    #pragma unroll
    for (int m = 0; m < 4; m++)
        #pragma unroll
        for (int n = 0; n < 4; n++)
            #pragma unroll
            for (int c = 0; c < 4; c++) acc[m][n][c] = 0.0f;

    const __nv_bfloat16* Ag = g_Ah + (long)b * BQ * DM;
    // per-lane x2 row pointers for the 4 n-tiles this warp owns
    const float* Xg = x2 + ((long)b * LKV + (long)ch * CKEYS) * DM;
    const int kf = (lane & 3) * 2;
    const float* xrow[4];
    #pragma unroll
    for (int n = 0; n < 4; n++)
        xrow[n] = Xg + (long)(w * 32 + n * 8 + (lane >> 2)) * DM;

    #pragma unroll
    for (int phase = 0; phase < 2; phase++) {
        // stage A half-k: 64 rows x 256 halfs (32 KB), uint4 copies
        __syncthreads();
        for (int i = tid; i < 64 * 32; i += 256) {
            int row = i >> 5, c8 = (i & 31) * 8;
            *(uint4*)&Avs[row][c8] =
                *(const uint4*)&Ag[(long)row * DM + phase * 256 + c8];
        }
        __syncthreads();

        #pragma unroll 4
        for (int k0 = 0; k0 < 256; k0 += 16) {
            const int kg = phase * 256 + k0;
            // B fragments straight from gmem
            unsigned bfr[4][2];
            #pragma unroll
            for (int n = 0; n < 4; n++) {
                float2 lo = *(const float2*)(xrow[n] + kg + kf);
                float2 hi = *(const float2*)(xrow[n] + kg + kf + 8);
                bfr[n][0] = bf2u(__float22bfloat162_rn(lo));
                bfr[n][1] = bf2u(__float22bfloat162_rn(hi));
            }
            // A fragments from resident smem
            unsigned afr[4][4];
            #pragma unroll
            for (int m = 0; m < 4; m++) {
                unsigned addr = (unsigned)__cvta_generic_to_shared(
                    &Avs[m * 16 + (lane & 15)][k0 + (lane >> 4) * 8]);
                asm volatile("ldmatrix.sync.aligned.m8n8.x4.shared.b16 {%0,%1,%2,%3}, [%4];"
                    : "=r"(afr[m][0]), "=r"(afr[m][1]), "=r"(afr[m][2]), "=r"(afr[m][3])
                    : "r"(addr));
            }
            #pragma unroll
            for (int m = 0; m < 4; m++)
                #pragma unroll
                for (int n = 0; n < 4; n++)
                    asm volatile(
                        "mma.sync.aligned.m16n8k16.row.col.f32.bf16.bf16.f32 "
                        "{%0,%1,%2,%3}, {%4,%5,%6,%7}, {%8,%9}, {%0,%1,%2,%3};"
                        : "+f"(acc[m][n][0]), "+f"(acc[m][n][1]),
                          "+f"(acc[m][n][2]), "+f"(acc[m][n][3])
                        : "r"(afr[m][0]), "r"(afr[m][1]), "r"(afr[m][2]), "r"(afr[m][3]),
                          "r"(bfr[n][0]), "r"(bfr[n][1]));
        }
    }
    __syncthreads();

    __nv_bfloat16* Sbase = g_Sh + (long)(b * BQ) * LKV + ch * CKEYS;
    const int qr = lane >> 2;
    const int c2 = (lane & 3) * 2;
    #pragma unroll
    for (int m = 0; m < 4; m++) {
        float m0 = -3.0e38f, m1 = -3.0e38f;
        #pragma unroll
        for (int n = 0; n < 4; n++) {
            int col = w * 32 + n * 8 + c2;
            *(__nv_bfloat162*)&Sbase[(long)(m * 16 + qr)     * LKV + col] =
                __float22bfloat162_rn(make_float2(acc[m][n][0], acc[m][n][1]));
            *(__nv_bfloat162*)&Sbase[(long)(m * 16 + qr + 8) * LKV + col] =
                __float22bfloat162_rn(make_float2(acc[m][n][2], acc[m][n][3]));
            m0 = fmaxf(m0, fmaxf(acc[m][n][0], acc[m][n][1]));
            m1 = fmaxf(m1, fmaxf(acc[m][n][2], acc[m][n][3]));
        }
        #pragma unroll
        for (int o = 1; o < 4; o <<= 1) {
            m0 = fmaxf(m0, __shfl_xor_sync(0xffffffffu, m0, o));
            m1 = fmaxf(m1, __shfl_xor_sync(0xffffffffu, m1, o));
        }
        if ((lane & 3) == 0) {
            atomicMax(&red[m * 16 + qr],     f2key(m0));
            atomicMax(&red[m * 16 + qr + 8], f2key(m1));
        }
    }
    __syncthreads();
    if (tid < 64) atomicMax(&g_M[b * BQ + tid], red[tid]);
}

// ---------------------------------------------------------------------------
// Select (bf16 S) + exact fp32 rescore + softmax + Y planes (unchanged).
// ---------------------------------------------------------------------------
__global__ void k_select(const float* __restrict__ x2)
{
    __shared__ int   candk[8][MAXC];
    __shared__ float cands[8][MAXC];
    const int w    = threadIdx.x >> 5;
    const int lane = threadIdx.x & 31;
    const int r    = blockIdx.x * 8 + w;
    const int b    = r / BQ;
    const float th = key2f(g_M[r]) - 23.0f;

    const uint4* Srow = (const uint4*)(g_Sh + (long)r * LKV);
    int cnt = 0;
    for (int it = 0; it < 16; it++) {
        uint4 v = Srow[it * 32 + lane];
        unsigned wd[4] = {v.x, v.y, v.z, v.w};
        #pragma unroll
        for (int q = 0; q < 4; q++) {
            __nv_bfloat162 p2 = *(__nv_bfloat162*)&wd[q];
            float sv0 = __bfloat162float(p2.x);
            float sv1 = __bfloat162float(p2.y);
            #pragma unroll
            for (int h = 0; h < 2; h++) {
                float sv = h ? sv1 : sv0;
                bool sel = sv > th;
                unsigned msk = __ballot_sync(0xffffffffu, sel);
                if (sel) {
                    int pos = cnt + __popc(msk & ((1u << lane) - 1u));
                    if (pos < MAXC) candk[w][pos] = (it * 32 + lane) * 8 + q * 2 + h;
                }
                cnt = min(cnt + __popc(msk), MAXC);
            }
        }
    }
    __syncwarp();

    const float* Arow = g_A + (long)r * DM;
    float a[16];
    #pragma unroll
    for (int i = 0; i < 16; i++) a[i] = Arow[i * 32 + lane];

    float me = -3.0e38f;
    for (int j = 0; j < cnt; j++) {
        const float* xr = x2 + ((long)b * LKV + candk[w][j]) * DM;
        float s = 0.0f;
        #pragma unroll
        for (int i = 0; i < 16; i++) s += a[i] * xr[i * 32 + lane];
        #pragma unroll
        for (int o = 16; o > 0; o >>= 1) s += __shfl_xor_sync(0xffffffffu, s, o);
        if (lane == 0) cands[w][j] = s;
        me = fmaxf(me, s);
    }
    __syncwarp();

    float y[16];
    #pragma unroll
    for (int i = 0; i < 16; i++) y[i] = 0.0f;
    float z = 0.0f;
    for (int j = 0; j < cnt; j++) {
        float p = expf(cands[w][j] - me);
        z += p;
        const float* xr = x2 + ((long)b * LKV + candk[w][j]) * DM;
        #pragma unroll
        for (int i = 0; i < 16; i++) y[i] += p * xr[i * 32 + lane];
    }
    float inv = 1.0f / z;
    #pragma unroll
    for (int i = 0; i < 16; i++) {
        float v = y[i] * inv;
        __nv_bfloat16 h0 = __float2bfloat16_rn(v);
        __nv_bfloat16 h1 = __float2bfloat16_rn(v - __bfloat162float(h0));
        g_Yh[0][(long)r * DM + i * 32 + lane] = h0;
        g_Yh[1][(long)r * DM + i * 32 + lane] = h1;
    }
}

// ---------------------------------------------------------------------------
extern "C" void kernel_launch(void* const* d_in, const int* in_sizes, int n_in,
                              void* d_out, int out_size)
{
    const float* x1 = (const float*)d_in[0];
    const float* x2 = (const float*)d_in[1];
    // d_in[2] = mask : unused in reference forward
    const float* wq = (const float*)d_in[3];
    const float* bq = (const float*)d_in[4];
    const float* wk = (const float*)d_in[5];
    // d_in[6] = bk : cancels in softmax (per-row constant)
    const float* wv = (const float*)d_in[7];
    const float* bv = (const float*)d_in[8];
    float* out = (float*)d_out;

    k_init<<<4, 512>>>();

    // parameter prep (independent, cheap)
    k_W<<<dim3(8, 8), 512>>>(wq, wk);                 // Wt planes (3)
    k_a2<<<2, 256>>>(wk, bq);                         // bias fold
    k_prep<3, 0><<<1024, 256>>>(x1);                  // x1 planes (3)
    k_prep<2, 1><<<256, 256>>>(wv);                   // wv planes (2)

    // A = x1 * Wt^T + a2  (3-split plane TC) -> g_A + g_Ah
    k_tc_nt<3, 6, 0><<<dim3(32, 8), 256>>>(nullptr, nullptr);

    // bf16 TC scores (B direct-from-gmem) + row maxima
    k_scores_tc<<<dim3(NB, NCHUNK), 256>>>(x2);

    // select + exact softmax + Y planes (2)
    k_select<<<NROWS / 8, 256>>>(x2);

    // out = Y * wv^T + bv  (2-split plane TC)
    k_tc_nt<2, 3, 1><<<dim3(32, 8), 256>>>(bv, out);
}